// round 3
// baseline (speedup 1.0000x reference)
#include <cuda_runtime.h>
#include <math.h>
#include <float.h>

// Problem constants
#define B_   4
#define T_   2048
#define C_   1024
#define H_   16
#define D_   64
#define BT_  (B_*T_)           // 8192
#define F3_  (3*C_)            // 3072

// Scratch (static device globals: alloc-free, graph-safe)
__device__ float g_qkv[(size_t)BT_ * F3_];        // [B*T, 3C]
__device__ float g_q[(size_t)B_*H_*T_*D_];        // [B,H,T,D]
__device__ float g_k[(size_t)B_*H_*T_*D_];
__device__ float g_v[(size_t)B_*H_*T_*D_];
__device__ float g_y[(size_t)BT_ * C_];           // [B,T,C]

// ---------------------------------------------------------------------------
// SGEMM: C[M,N] = A[M,K] @ B[K,N], row-major, fp32. Tiles 128x128, BK=8,
// 256 threads, 8x8 micro-tile. Double-buffered smem, one sync per K-step.
// ---------------------------------------------------------------------------
__global__ __launch_bounds__(256) void sgemm_k(
    const float* __restrict__ A, const float* __restrict__ B,
    float* __restrict__ C, int M, int N, int K)
{
    __shared__ float As[2][8][128];
    __shared__ float Bs[2][8][128];

    const int tid = threadIdx.x;
    const int bm = blockIdx.y * 128;
    const int bn = blockIdx.x * 128;

    const int a_row = tid >> 1;           // 0..127
    const int a_col = (tid & 1) * 4;      // 0 or 4
    const int b_row = tid >> 5;           // 0..7
    const int b_col = (tid & 31) * 4;     // 0..124

    const float* Aptr = A + (size_t)(bm + a_row) * K + a_col;
    const float* Bptr = B + (size_t)b_row * N + bn + b_col;

    const int tm = (tid >> 4) * 8;        // 0..120
    const int tn = (tid & 15) * 8;        // 0..120

    float acc[8][8];
#pragma unroll
    for (int i = 0; i < 8; ++i)
#pragma unroll
        for (int j = 0; j < 8; ++j) acc[i][j] = 0.f;

    // Preload tile 0
    {
        float4 av = *(const float4*)Aptr;  Aptr += 8;
        float4 bv = *(const float4*)Bptr;  Bptr += (size_t)8 * N;
        As[0][a_col + 0][a_row] = av.x;
        As[0][a_col + 1][a_row] = av.y;
        As[0][a_col + 2][a_row] = av.z;
        As[0][a_col + 3][a_row] = av.w;
        *(float4*)&Bs[0][b_row][b_col] = bv;
    }
    __syncthreads();

    const int ntiles = K >> 3;
    int buf = 0;
    for (int t = 0; t < ntiles; ++t) {
        const bool has_next = (t + 1 < ntiles);
        float4 av2, bv2;
        if (has_next) {
            av2 = *(const float4*)Aptr;  Aptr += 8;
            bv2 = *(const float4*)Bptr;  Bptr += (size_t)8 * N;
        }

#pragma unroll
        for (int kk = 0; kk < 8; ++kk) {
            float4 a0 = *(const float4*)&As[buf][kk][tm];
            float4 a1 = *(const float4*)&As[buf][kk][tm + 4];
            float4 b0 = *(const float4*)&Bs[buf][kk][tn];
            float4 b1 = *(const float4*)&Bs[buf][kk][tn + 4];
            float ar[8] = {a0.x,a0.y,a0.z,a0.w,a1.x,a1.y,a1.z,a1.w};
            float br[8] = {b0.x,b0.y,b0.z,b0.w,b1.x,b1.y,b1.z,b1.w};
#pragma unroll
            for (int i = 0; i < 8; ++i)
#pragma unroll
                for (int j = 0; j < 8; ++j)
                    acc[i][j] = fmaf(ar[i], br[j], acc[i][j]);
        }

        if (has_next) {
            const int nb = buf ^ 1;
            As[nb][a_col + 0][a_row] = av2.x;
            As[nb][a_col + 1][a_row] = av2.y;
            As[nb][a_col + 2][a_row] = av2.z;
            As[nb][a_col + 3][a_row] = av2.w;
            *(float4*)&Bs[nb][b_row][b_col] = bv2;
        }
        __syncthreads();
        buf ^= 1;
    }

#pragma unroll
    for (int i = 0; i < 8; ++i) {
        float* Crow = C + (size_t)(bm + tm + i) * N + bn + tn;
        float4 c0 = {acc[i][0], acc[i][1], acc[i][2], acc[i][3]};
        float4 c1 = {acc[i][4], acc[i][5], acc[i][6], acc[i][7]};
        *(float4*)(Crow)     = c0;
        *(float4*)(Crow + 4) = c1;
    }
}

// ---------------------------------------------------------------------------
// RoPE + split + transpose: qkv[B,T,3C] -> q,k (roped) and v in [B,H,T,D]
// ---------------------------------------------------------------------------
__global__ void rope_split_k(const float* __restrict__ qkv,
                             float* __restrict__ q,
                             float* __restrict__ k,
                             float* __restrict__ v)
{
    const int idx = blockIdx.x * blockDim.x + threadIdx.x;  // B*T*H*32 total
    const int p = idx & 31;
    const int h = (idx >> 5) & 15;
    const int t = (idx >> 9) & 2047;
    const int b = idx >> 20;

    const float* base = qkv + (size_t)(b * T_ + t) * F3_;
    const int c = h * D_ + 2 * p;

    const float q1 = base[c],          q2 = base[c + 1];
    const float k1 = base[C_ + c],     k2 = base[C_ + c + 1];
    const float v1 = base[2*C_ + c],   v2 = base[2*C_ + c + 1];

    const float inv = exp2f(-(float)(2 * p) * (13.287712379549449f / 64.f));
    const float ang = (float)t * inv;
    float sn, cs;
    sincosf(ang, &sn, &cs);

    const size_t o = ((size_t)((b * H_ + h) * T_ + t)) * D_ + 2 * p;
    q[o]     = q1 * cs - q2 * sn;
    q[o + 1] = q1 * sn + q2 * cs;
    k[o]     = k1 * cs - k2 * sn;
    k[o + 1] = k1 * sn + k2 * cs;
    v[o]     = v1;
    v[o + 1] = v2;
}

// ---------------------------------------------------------------------------
// Causal flash attention, fp32, vectorized LDS.128 inner loops.
// One block per (q_tile=64 rows, head, batch). 256 threads, 4x4 micro-tiles.
// K/P tile stride = 68 floats (16B-aligned rows, conflict-free in 8-lane
// phases: 68 mod 32 = 4, distinct banks for r mod 8). P aliases K after S.
// ---------------------------------------------------------------------------
#define KPS 68
#define ATT_SMEM ((64*64 + 64*KPS + 64*64) * 4)   // 50176 bytes

__global__ __launch_bounds__(256) void attn_k(
    const float* __restrict__ Q, const float* __restrict__ K,
    const float* __restrict__ V, float* __restrict__ Y)
{
    extern __shared__ float sm[];
    float* Qs = sm;               // [64][64]
    float* KP = sm + 64*64;       // [64][KPS]  (K tile, later P tile)
    float* Vs = KP + 64*KPS;      // [64][64]

    // Longest blocks (largest qt) first to shrink the wave tail.
    const int qt = (int)gridDim.x - 1 - (int)blockIdx.x;   // 0..31
    const int h  = blockIdx.y;
    const int b  = blockIdx.z;
    const int bh = b * H_ + h;

    const float* Qp = Q + (size_t)bh * T_ * D_;
    const float* Kp = K + (size_t)bh * T_ * D_;
    const float* Vp = V + (size_t)bh * T_ * D_;

    const int tid = threadIdx.x;
    const int tm = tid >> 4;      // 0..15
    const int tn = tid & 15;      // 0..15
    const int tm4 = tm * 4, tn4 = tn * 4;
    const int q0 = qt * 64;

    const int lr = tid >> 4;              // loader row within pass
    const int lc = (tid & 15) * 4;        // loader col (float4)

    // Load Q tile
#pragma unroll
    for (int ps = 0; ps < 4; ++ps) {
        int r = ps * 16 + lr;
        *(float4*)&Qs[r * 64 + lc] = *(const float4*)&Qp[(size_t)(q0 + r) * D_ + lc];
    }

    float m[4], l[4], o[4][4];
#pragma unroll
    for (int i = 0; i < 4; ++i) {
        m[i] = -INFINITY; l[i] = 0.f;
#pragma unroll
        for (int j = 0; j < 4; ++j) o[i][j] = 0.f;
    }

    for (int kt = 0; kt <= qt; ++kt) {
        const int k0 = kt * 64;
        __syncthreads();   // previous iteration done with KP(=P) and Vs

        // Load K (stride KPS) and V tiles
#pragma unroll
        for (int ps = 0; ps < 4; ++ps) {
            int r = ps * 16 + lr;
            *(float4*)&KP[r * KPS + lc] = *(const float4*)&Kp[(size_t)(k0 + r) * D_ + lc];
            *(float4*)&Vs[r * 64  + lc] = *(const float4*)&Vp[(size_t)(k0 + r) * D_ + lc];
        }
        __syncthreads();

        // S = Q @ K^T  (vectorized over d, 8x LDS.128 + 64 FFMA per 4 d)
        float s[4][4];
#pragma unroll
        for (int i = 0; i < 4; ++i)
#pragma unroll
            for (int j = 0; j < 4; ++j) s[i][j] = 0.f;

#pragma unroll 4
        for (int d = 0; d < 64; d += 4) {
            float4 a0 = *(const float4*)&Qs[(tm4 + 0) * 64 + d];
            float4 a1 = *(const float4*)&Qs[(tm4 + 1) * 64 + d];
            float4 a2 = *(const float4*)&Qs[(tm4 + 2) * 64 + d];
            float4 a3 = *(const float4*)&Qs[(tm4 + 3) * 64 + d];
            float4 b0 = *(const float4*)&KP[(tn4 + 0) * KPS + d];
            float4 b1 = *(const float4*)&KP[(tn4 + 1) * KPS + d];
            float4 b2 = *(const float4*)&KP[(tn4 + 2) * KPS + d];
            float4 b3 = *(const float4*)&KP[(tn4 + 3) * KPS + d];
#define SDOT(i, A) \
            s[i][0] = fmaf(A.x,b0.x, fmaf(A.y,b0.y, fmaf(A.z,b0.z, fmaf(A.w,b0.w, s[i][0])))); \
            s[i][1] = fmaf(A.x,b1.x, fmaf(A.y,b1.y, fmaf(A.z,b1.z, fmaf(A.w,b1.w, s[i][1])))); \
            s[i][2] = fmaf(A.x,b2.x, fmaf(A.y,b2.y, fmaf(A.z,b2.z, fmaf(A.w,b2.w, s[i][2])))); \
            s[i][3] = fmaf(A.x,b3.x, fmaf(A.y,b3.y, fmaf(A.z,b3.z, fmaf(A.w,b3.w, s[i][3]))));
            SDOT(0, a0) SDOT(1, a1) SDOT(2, a2) SDOT(3, a3)
#undef SDOT
        }

        const float scale = 0.125f;   // 1/sqrt(64)
#pragma unroll
        for (int i = 0; i < 4; ++i)
#pragma unroll
            for (int j = 0; j < 4; ++j) s[i][j] *= scale;

        if (kt == qt) {   // diagonal tile: causal mask
#pragma unroll
            for (int i = 0; i < 4; ++i)
#pragma unroll
                for (int j = 0; j < 4; ++j)
                    if (k0 + tn4 + j > q0 + tm4 + i) s[i][j] = -INFINITY;
        }

        // Row max over the 16 tn lanes
        float rmax[4];
#pragma unroll
        for (int i = 0; i < 4; ++i)
            rmax[i] = fmaxf(fmaxf(s[i][0], s[i][1]), fmaxf(s[i][2], s[i][3]));
#pragma unroll
        for (int off = 8; off >= 1; off >>= 1)
#pragma unroll
            for (int i = 0; i < 4; ++i)
                rmax[i] = fmaxf(rmax[i], __shfl_xor_sync(0xffffffffu, rmax[i], off));

        float alpha[4], rsum[4];
#pragma unroll
        for (int i = 0; i < 4; ++i) {
            float mn = fmaxf(m[i], rmax[i]);
            alpha[i] = __expf(m[i] - mn);
            m[i] = mn;
            rsum[i] = 0.f;
#pragma unroll
            for (int j = 0; j < 4; ++j) {
                s[i][j] = __expf(s[i][j] - mn);
                rsum[i] += s[i][j];
            }
        }
#pragma unroll
        for (int off = 8; off >= 1; off >>= 1)
#pragma unroll
            for (int i = 0; i < 4; ++i)
                rsum[i] += __shfl_xor_sync(0xffffffffu, rsum[i], off);

#pragma unroll
        for (int i = 0; i < 4; ++i) {
            l[i] = l[i] * alpha[i] + rsum[i];
#pragma unroll
            for (int j = 0; j < 4; ++j) o[i][j] *= alpha[i];
        }

        __syncthreads();   // everyone done reading KP as K
        // Write P into KP (float4 rows)
#pragma unroll
        for (int i = 0; i < 4; ++i) {
            float4 w = {s[i][0], s[i][1], s[i][2], s[i][3]};
            *(float4*)&KP[(tm4 + i) * KPS + tn4] = w;
        }
        __syncthreads();

        // O += P @ V  (vectorized over jj, 8x LDS.128 + 64 FFMA per 4 jj)
#pragma unroll 4
        for (int jj = 0; jj < 64; jj += 4) {
            float4 p0 = *(const float4*)&KP[(tm4 + 0) * KPS + jj];
            float4 p1 = *(const float4*)&KP[(tm4 + 1) * KPS + jj];
            float4 p2 = *(const float4*)&KP[(tm4 + 2) * KPS + jj];
            float4 p3 = *(const float4*)&KP[(tm4 + 3) * KPS + jj];
            float4 v0 = *(const float4*)&Vs[(jj + 0) * 64 + tn4];
            float4 v1 = *(const float4*)&Vs[(jj + 1) * 64 + tn4];
            float4 v2 = *(const float4*)&Vs[(jj + 2) * 64 + tn4];
            float4 v3 = *(const float4*)&Vs[(jj + 3) * 64 + tn4];
#define PDOT(i, P) \
            o[i][0] = fmaf(P.x,v0.x, fmaf(P.y,v1.x, fmaf(P.z,v2.x, fmaf(P.w,v3.x, o[i][0])))); \
            o[i][1] = fmaf(P.x,v0.y, fmaf(P.y,v1.y, fmaf(P.z,v2.y, fmaf(P.w,v3.y, o[i][1])))); \
            o[i][2] = fmaf(P.x,v0.z, fmaf(P.y,v1.z, fmaf(P.z,v2.z, fmaf(P.w,v3.z, o[i][2])))); \
            o[i][3] = fmaf(P.x,v0.w, fmaf(P.y,v1.w, fmaf(P.z,v2.w, fmaf(P.w,v3.w, o[i][3]))));
            PDOT(0, p0) PDOT(1, p1) PDOT(2, p2) PDOT(3, p3)
#undef PDOT
        }
    }

    // Epilogue: normalize, write y as [B,T,H,D] == [B,T,C]
#pragma unroll
    for (int i = 0; i < 4; ++i) {
        const float inv = 1.f / l[i];
        const int t = q0 + tm4 + i;
        float4 w = {o[i][0]*inv, o[i][1]*inv, o[i][2]*inv, o[i][3]*inv};
        *(float4*)(Y + ((size_t)(b * T_ + t) * H_ + h) * D_ + tn4) = w;
    }
}

// ---------------------------------------------------------------------------
extern "C" void kernel_launch(void* const* d_in, const int* in_sizes, int n_in,
                              void* d_out, int out_size)
{
    const float* x      = (const float*)d_in[0];   // [B,T,C]
    const float* W_attn = (const float*)d_in[1];   // [C,3C]
    const float* W_proj = (const float*)d_in[2];   // [C,C]
    float* out = (float*)d_out;                    // [B,T,C]

    float *qkv, *q, *k, *v, *y;
    cudaGetSymbolAddress((void**)&qkv, g_qkv);
    cudaGetSymbolAddress((void**)&q,   g_q);
    cudaGetSymbolAddress((void**)&k,   g_k);
    cudaGetSymbolAddress((void**)&v,   g_v);
    cudaGetSymbolAddress((void**)&y,   g_y);

    cudaFuncSetAttribute(attn_k, cudaFuncAttributeMaxDynamicSharedMemorySize, ATT_SMEM);

    // 1) QKV GEMM: [8192,1024] @ [1024,3072]
    {
        dim3 grid(F3_ / 128, BT_ / 128);
        sgemm_k<<<grid, 256>>>(x, W_attn, qkv, BT_, F3_, C_);
    }
    // 2) RoPE + split/transpose
    {
        int total = B_ * T_ * H_ * (D_ / 2);   // 4,194,304
        rope_split_k<<<total / 256, 256>>>(qkv, q, k, v);
    }
    // 3) Causal flash attention
    {
        dim3 grid(T_ / 64, H_, B_);
        attn_k<<<grid, 256, ATT_SMEM>>>(q, k, v, y);
    }
    // 4) Projection GEMM: [8192,1024] @ [1024,1024]
    {
        dim3 grid(C_ / 128, BT_ / 128);
        sgemm_k<<<grid, 256>>>(y, W_proj, out, BT_, C_, C_);
    }
}

// round 4
// speedup vs baseline: 1.2821x; 1.2821x over previous
#include <cuda_runtime.h>
#include <math.h>
#include <float.h>

// Problem constants
#define B_   4
#define T_   2048
#define C_   1024
#define H_   16
#define D_   64
#define BT_  (B_*T_)           // 8192
#define F3_  (3*C_)            // 3072

// Scratch (static device globals: alloc-free, graph-safe)
__device__ float g_qkv[(size_t)BT_ * F3_];        // [B*T, 3C]
__device__ float g_q[(size_t)B_*H_*T_*D_];        // [B,H,T,D]
__device__ float g_k[(size_t)B_*H_*T_*D_];
__device__ float g_v[(size_t)B_*H_*T_*D_];
__device__ float g_y[(size_t)BT_ * C_];           // [B,T,C]

// ---------------------------------------------------------------------------
// SGEMM: C[M,N] = A[M,K] @ B[K,N], row-major, fp32. Tiles 128x128, BK=8,
// 256 threads, 8x8 micro-tile. Double-buffered smem, one sync per K-step.
// ---------------------------------------------------------------------------
__global__ __launch_bounds__(256) void sgemm_k(
    const float* __restrict__ A, const float* __restrict__ B,
    float* __restrict__ C, int M, int N, int K)
{
    __shared__ float As[2][8][128];
    __shared__ float Bs[2][8][128];

    const int tid = threadIdx.x;
    const int bm = blockIdx.y * 128;
    const int bn = blockIdx.x * 128;

    const int a_row = tid >> 1;           // 0..127
    const int a_col = (tid & 1) * 4;      // 0 or 4
    const int b_row = tid >> 5;           // 0..7
    const int b_col = (tid & 31) * 4;     // 0..124

    const float* Aptr = A + (size_t)(bm + a_row) * K + a_col;
    const float* Bptr = B + (size_t)b_row * N + bn + b_col;

    const int tm = (tid >> 4) * 8;        // 0..120
    const int tn = (tid & 15) * 8;        // 0..120

    float acc[8][8];
#pragma unroll
    for (int i = 0; i < 8; ++i)
#pragma unroll
        for (int j = 0; j < 8; ++j) acc[i][j] = 0.f;

    // Preload tile 0
    {
        float4 av = *(const float4*)Aptr;  Aptr += 8;
        float4 bv = *(const float4*)Bptr;  Bptr += (size_t)8 * N;
        As[0][a_col + 0][a_row] = av.x;
        As[0][a_col + 1][a_row] = av.y;
        As[0][a_col + 2][a_row] = av.z;
        As[0][a_col + 3][a_row] = av.w;
        *(float4*)&Bs[0][b_row][b_col] = bv;
    }
    __syncthreads();

    const int ntiles = K >> 3;
    int buf = 0;
    for (int t = 0; t < ntiles; ++t) {
        const bool has_next = (t + 1 < ntiles);
        float4 av2, bv2;
        if (has_next) {
            av2 = *(const float4*)Aptr;  Aptr += 8;
            bv2 = *(const float4*)Bptr;  Bptr += (size_t)8 * N;
        }

#pragma unroll
        for (int kk = 0; kk < 8; ++kk) {
            float4 a0 = *(const float4*)&As[buf][kk][tm];
            float4 a1 = *(const float4*)&As[buf][kk][tm + 4];
            float4 b0 = *(const float4*)&Bs[buf][kk][tn];
            float4 b1 = *(const float4*)&Bs[buf][kk][tn + 4];
            float ar[8] = {a0.x,a0.y,a0.z,a0.w,a1.x,a1.y,a1.z,a1.w};
            float br[8] = {b0.x,b0.y,b0.z,b0.w,b1.x,b1.y,b1.z,b1.w};
#pragma unroll
            for (int i = 0; i < 8; ++i)
#pragma unroll
                for (int j = 0; j < 8; ++j)
                    acc[i][j] = fmaf(ar[i], br[j], acc[i][j]);
        }

        if (has_next) {
            const int nb = buf ^ 1;
            As[nb][a_col + 0][a_row] = av2.x;
            As[nb][a_col + 1][a_row] = av2.y;
            As[nb][a_col + 2][a_row] = av2.z;
            As[nb][a_col + 3][a_row] = av2.w;
            *(float4*)&Bs[nb][b_row][b_col] = bv2;
        }
        __syncthreads();
        buf ^= 1;
    }

#pragma unroll
    for (int i = 0; i < 8; ++i) {
        float* Crow = C + (size_t)(bm + tm + i) * N + bn + tn;
        float4 c0 = {acc[i][0], acc[i][1], acc[i][2], acc[i][3]};
        float4 c1 = {acc[i][4], acc[i][5], acc[i][6], acc[i][7]};
        *(float4*)(Crow)     = c0;
        *(float4*)(Crow + 4) = c1;
    }
}

// ---------------------------------------------------------------------------
// RoPE + split + transpose: qkv[B,T,3C] -> q,k (roped) and v in [B,H,T,D]
// ---------------------------------------------------------------------------
__global__ void rope_split_k(const float* __restrict__ qkv,
                             float* __restrict__ q,
                             float* __restrict__ k,
                             float* __restrict__ v)
{
    const int idx = blockIdx.x * blockDim.x + threadIdx.x;  // B*T*H*32 total
    const int p = idx & 31;
    const int h = (idx >> 5) & 15;
    const int t = (idx >> 9) & 2047;
    const int b = idx >> 20;

    const float* base = qkv + (size_t)(b * T_ + t) * F3_;
    const int c = h * D_ + 2 * p;

    const float q1 = base[c],          q2 = base[c + 1];
    const float k1 = base[C_ + c],     k2 = base[C_ + c + 1];
    const float v1 = base[2*C_ + c],   v2 = base[2*C_ + c + 1];

    const float inv = exp2f(-(float)(2 * p) * (13.287712379549449f / 64.f));
    const float ang = (float)t * inv;
    float sn, cs;
    sincosf(ang, &sn, &cs);

    const size_t o = ((size_t)((b * H_ + h) * T_ + t)) * D_ + 2 * p;
    q[o]     = q1 * cs - q2 * sn;
    q[o + 1] = q1 * sn + q2 * cs;
    k[o]     = k1 * cs - k2 * sn;
    k[o + 1] = k1 * sn + k2 * cs;
    v[o]     = v1;
    v[o + 1] = v2;
}

// ---------------------------------------------------------------------------
// Causal flash attention, fp32, vectorized LDS.128 inner loops.
// One block per (q_tile=64 rows, head, batch). 256 threads, 4x4 micro-tiles.
// S-phase column mapping is INTERLEAVED (col = tn + 16*j) so the per-lane
// K-row spacing is 1 -> with stride KPS=68 the float4 loads are bank-
// conflict-free (68 mod 32 = 4 banks/row). Output/V columns stay contiguous
// (tn*4+j). P aliases the K buffer after S is computed.
// ---------------------------------------------------------------------------
#define KPS 68
#define ATT_SMEM ((64*64 + 64*KPS + 64*64) * 4)   // 50176 bytes

__global__ __launch_bounds__(256) void attn_k(
    const float* __restrict__ Q, const float* __restrict__ K,
    const float* __restrict__ V, float* __restrict__ Y)
{
    extern __shared__ float sm[];
    float* Qs = sm;               // [64][64]
    float* KP = sm + 64*64;       // [64][KPS]  (K tile, later P tile)
    float* Vs = KP + 64*KPS;      // [64][64]

    // Longest blocks (largest qt) first to shrink the wave tail.
    const int qt = (int)gridDim.x - 1 - (int)blockIdx.x;   // 0..31
    const int h  = blockIdx.y;
    const int b  = blockIdx.z;
    const int bh = b * H_ + h;

    const float* Qp = Q + (size_t)bh * T_ * D_;
    const float* Kp = K + (size_t)bh * T_ * D_;
    const float* Vp = V + (size_t)bh * T_ * D_;

    const int tid = threadIdx.x;
    const int tm = tid >> 4;      // 0..15
    const int tn = tid & 15;      // 0..15
    const int tm4 = tm * 4, tn4 = tn * 4;
    const int q0 = qt * 64;

    const int lr = tid >> 4;              // loader row within pass
    const int lc = (tid & 15) * 4;        // loader col (float4)

    // Load Q tile
#pragma unroll
    for (int ps = 0; ps < 4; ++ps) {
        int r = ps * 16 + lr;
        *(float4*)&Qs[r * 64 + lc] = *(const float4*)&Qp[(size_t)(q0 + r) * D_ + lc];
    }

    float m[4], l[4], o[4][4];
#pragma unroll
    for (int i = 0; i < 4; ++i) {
        m[i] = -INFINITY; l[i] = 0.f;
#pragma unroll
        for (int j = 0; j < 4; ++j) o[i][j] = 0.f;
    }

    for (int kt = 0; kt <= qt; ++kt) {
        const int k0 = kt * 64;
        __syncthreads();   // previous iteration done with KP(=P) and Vs

        // Load K (stride KPS) and V tiles
#pragma unroll
        for (int ps = 0; ps < 4; ++ps) {
            int r = ps * 16 + lr;
            *(float4*)&KP[r * KPS + lc] = *(const float4*)&Kp[(size_t)(k0 + r) * D_ + lc];
            *(float4*)&Vs[r * 64  + lc] = *(const float4*)&Vp[(size_t)(k0 + r) * D_ + lc];
        }
        __syncthreads();

        // S = Q @ K^T. s[i][j] is S[q0+tm4+i][k0 + tn + 16*j] (interleaved cols)
        float s[4][4];
#pragma unroll
        for (int i = 0; i < 4; ++i)
#pragma unroll
            for (int j = 0; j < 4; ++j) s[i][j] = 0.f;

#pragma unroll 4
        for (int d = 0; d < 64; d += 4) {
            float4 a0 = *(const float4*)&Qs[(tm4 + 0) * 64 + d];
            float4 a1 = *(const float4*)&Qs[(tm4 + 1) * 64 + d];
            float4 a2 = *(const float4*)&Qs[(tm4 + 2) * 64 + d];
            float4 a3 = *(const float4*)&Qs[(tm4 + 3) * 64 + d];
            float4 b0 = *(const float4*)&KP[(tn +  0) * KPS + d];
            float4 b1 = *(const float4*)&KP[(tn + 16) * KPS + d];
            float4 b2 = *(const float4*)&KP[(tn + 32) * KPS + d];
            float4 b3 = *(const float4*)&KP[(tn + 48) * KPS + d];
#define SDOT(i, A) \
            s[i][0] = fmaf(A.x,b0.x, fmaf(A.y,b0.y, fmaf(A.z,b0.z, fmaf(A.w,b0.w, s[i][0])))); \
            s[i][1] = fmaf(A.x,b1.x, fmaf(A.y,b1.y, fmaf(A.z,b1.z, fmaf(A.w,b1.w, s[i][1])))); \
            s[i][2] = fmaf(A.x,b2.x, fmaf(A.y,b2.y, fmaf(A.z,b2.z, fmaf(A.w,b2.w, s[i][2])))); \
            s[i][3] = fmaf(A.x,b3.x, fmaf(A.y,b3.y, fmaf(A.z,b3.z, fmaf(A.w,b3.w, s[i][3]))));
            SDOT(0, a0) SDOT(1, a1) SDOT(2, a2) SDOT(3, a3)
#undef SDOT
        }

        const float scale = 0.125f;   // 1/sqrt(64)
#pragma unroll
        for (int i = 0; i < 4; ++i)
#pragma unroll
            for (int j = 0; j < 4; ++j) s[i][j] *= scale;

        if (kt == qt) {   // diagonal tile: causal mask (col = k0 + tn + 16j)
#pragma unroll
            for (int i = 0; i < 4; ++i)
#pragma unroll
                for (int j = 0; j < 4; ++j)
                    if (k0 + tn + 16*j > q0 + tm4 + i) s[i][j] = -INFINITY;
        }

        // Row max over the 16 tn lanes
        float rmax[4];
#pragma unroll
        for (int i = 0; i < 4; ++i)
            rmax[i] = fmaxf(fmaxf(s[i][0], s[i][1]), fmaxf(s[i][2], s[i][3]));
#pragma unroll
        for (int off = 8; off >= 1; off >>= 1)
#pragma unroll
            for (int i = 0; i < 4; ++i)
                rmax[i] = fmaxf(rmax[i], __shfl_xor_sync(0xffffffffu, rmax[i], off));

        float alpha[4], rsum[4];
#pragma unroll
        for (int i = 0; i < 4; ++i) {
            float mn = fmaxf(m[i], rmax[i]);
            alpha[i] = __expf(m[i] - mn);
            m[i] = mn;
            rsum[i] = 0.f;
#pragma unroll
            for (int j = 0; j < 4; ++j) {
                s[i][j] = __expf(s[i][j] - mn);
                rsum[i] += s[i][j];
            }
        }
#pragma unroll
        for (int off = 8; off >= 1; off >>= 1)
#pragma unroll
            for (int i = 0; i < 4; ++i)
                rsum[i] += __shfl_xor_sync(0xffffffffu, rsum[i], off);

#pragma unroll
        for (int i = 0; i < 4; ++i) {
            l[i] = l[i] * alpha[i] + rsum[i];
#pragma unroll
            for (int j = 0; j < 4; ++j) o[i][j] *= alpha[i];
        }

        __syncthreads();   // everyone done reading KP as K
        // Scatter P into KP at interleaved columns (conflict-free: banks
        // (16*tm + tn) mod 32 all distinct within a warp)
#pragma unroll
        for (int i = 0; i < 4; ++i)
#pragma unroll
            for (int j = 0; j < 4; ++j)
                KP[(tm4 + i) * KPS + tn + 16*j] = s[i][j];
        __syncthreads();

        // O += P @ V  (P float4 reads are per-phase broadcasts; V float4
        // reads at tn4 hit distinct banks). Output cols contiguous tn4+j.
#pragma unroll 4
        for (int jj = 0; jj < 64; jj += 4) {
            float4 p0 = *(const float4*)&KP[(tm4 + 0) * KPS + jj];
            float4 p1 = *(const float4*)&KP[(tm4 + 1) * KPS + jj];
            float4 p2 = *(const float4*)&KP[(tm4 + 2) * KPS + jj];
            float4 p3 = *(const float4*)&KP[(tm4 + 3) * KPS + jj];
            float4 v0 = *(const float4*)&Vs[(jj + 0) * 64 + tn4];
            float4 v1 = *(const float4*)&Vs[(jj + 1) * 64 + tn4];
            float4 v2 = *(const float4*)&Vs[(jj + 2) * 64 + tn4];
            float4 v3 = *(const float4*)&Vs[(jj + 3) * 64 + tn4];
#define PDOT(i, P) \
            o[i][0] = fmaf(P.x,v0.x, fmaf(P.y,v1.x, fmaf(P.z,v2.x, fmaf(P.w,v3.x, o[i][0])))); \
            o[i][1] = fmaf(P.x,v0.y, fmaf(P.y,v1.y, fmaf(P.z,v2.y, fmaf(P.w,v3.y, o[i][1])))); \
            o[i][2] = fmaf(P.x,v0.z, fmaf(P.y,v1.z, fmaf(P.z,v2.z, fmaf(P.w,v3.z, o[i][2])))); \
            o[i][3] = fmaf(P.x,v0.w, fmaf(P.y,v1.w, fmaf(P.z,v2.w, fmaf(P.w,v3.w, o[i][3]))));
            PDOT(0, p0) PDOT(1, p1) PDOT(2, p2) PDOT(3, p3)
#undef PDOT
        }
    }

    // Epilogue: normalize, write y as [B,T,H,D] == [B,T,C]
#pragma unroll
    for (int i = 0; i < 4; ++i) {
        const float inv = 1.f / l[i];
        const int t = q0 + tm4 + i;
        float4 w = {o[i][0]*inv, o[i][1]*inv, o[i][2]*inv, o[i][3]*inv};
        *(float4*)(Y + ((size_t)(b * T_ + t) * H_ + h) * D_ + tn4) = w;
    }
}

// ---------------------------------------------------------------------------
extern "C" void kernel_launch(void* const* d_in, const int* in_sizes, int n_in,
                              void* d_out, int out_size)
{
    const float* x      = (const float*)d_in[0];   // [B,T,C]
    const float* W_attn = (const float*)d_in[1];   // [C,3C]
    const float* W_proj = (const float*)d_in[2];   // [C,C]
    float* out = (float*)d_out;                    // [B,T,C]

    float *qkv, *q, *k, *v, *y;
    cudaGetSymbolAddress((void**)&qkv, g_qkv);
    cudaGetSymbolAddress((void**)&q,   g_q);
    cudaGetSymbolAddress((void**)&k,   g_k);
    cudaGetSymbolAddress((void**)&v,   g_v);
    cudaGetSymbolAddress((void**)&y,   g_y);

    cudaFuncSetAttribute(attn_k, cudaFuncAttributeMaxDynamicSharedMemorySize, ATT_SMEM);

    // 1) QKV GEMM: [8192,1024] @ [1024,3072]
    {
        dim3 grid(F3_ / 128, BT_ / 128);
        sgemm_k<<<grid, 256>>>(x, W_attn, qkv, BT_, F3_, C_);
    }
    // 2) RoPE + split/transpose
    {
        int total = B_ * T_ * H_ * (D_ / 2);   // 4,194,304
        rope_split_k<<<total / 256, 256>>>(qkv, q, k, v);
    }
    // 3) Causal flash attention
    {
        dim3 grid(T_ / 64, H_, B_);
        attn_k<<<grid, 256, ATT_SMEM>>>(q, k, v, y);
    }
    // 4) Projection GEMM: [8192,1024] @ [1024,1024]
    {
        dim3 grid(C_ / 128, BT_ / 128);
        sgemm_k<<<grid, 256>>>(y, W_proj, out, BT_, C_, C_);
    }
}